// round 12
// baseline (speedup 1.0000x reference)
#include <cuda_runtime.h>
#include <cuda_bf16.h>

#define NB 4096
#define NS 256
#define NQ 4          // batches per CTA

// histogram layout: job[11] @0, rep[34] @11, place[19] @45, add[31] @64 -> 95 (pad 96)
#define H_JOB 0
#define H_REP 11
#define H_PLACE 45
#define H_ADD 64

__global__ __launch_bounds__(256, 6)
void fused4_kernel(const float* __restrict__ cont_p, const float* __restrict__ cont_c,
                   const int* __restrict__ cat_p, const int* __restrict__ cat_c,
                   const int* __restrict__ lengths,
                   const float* __restrict__ w_p1, const float* __restrict__ b_p1,
                   const float* __restrict__ w_p2, const float* __restrict__ b_p2,
                   const float* __restrict__ w_c1, const float* __restrict__ b_c1,
                   const float* __restrict__ w_c2, const float* __restrict__ b_c2,
                   const float* __restrict__ eg, const float* __restrict__ ek,
                   const float* __restrict__ epr, const float* __restrict__ ejob,
                   const float* __restrict__ erep, const float* __restrict__ epl,
                   const float* __restrict__ eadd,
                   const float* __restrict__ w_fc1, const float* __restrict__ b_fc1,
                   const float* __restrict__ w_fc2, const float* __restrict__ b_fc2,
                   float* __restrict__ out)
{
    const int tid = threadIdx.x;
    const int lane = tid & 31;
    const int w = tid >> 5;
    const int b0 = blockIdx.x * NQ;
    const int q = w >> 1;          // warp's batch (0..3)
    const int h = w & 1;           // warp's half (0/1)

    __shared__ float4 s_t4[NQ][NS];      // 16 KB {x0,x1,x2,y0}
    __shared__ float  s_y1[NQ][NS];      // 4 KB
    __shared__ int    s_hist[NQ][96];    // 1.5 KB
    __shared__ unsigned s_binpack[NQ];
    __shared__ float s_redA[NQ][2][32];
    __shared__ float s_redC[NQ][2][32];
    __shared__ float s_apsum[NQ][32];
    __shared__ float s_acsum[NQ][32];
    __shared__ float s_pool[NQ][128];    // 2 KB
    __shared__ float s_part[NQ][4][64];  // 4 KB
    __shared__ float s_h1[NQ][64];       // 1 KB

    for (int i = tid; i < NQ * 96; i += 256) ((int*)s_hist)[i] = 0;
    if (tid < NQ) s_binpack[tid] = 0u;
    __syncthreads();

    const int lenq = lengths[b0 + q];    // uniform per warp (broadcast)

    // ---- Phase A: thread j owns tokens 4j..4j+3 of batch q; all-vector loads,
    //      compile-time column mapping, combined-format smem writes, plain atomics ----
    {
        const int j = h * 32 + lane;     // 0..63 within batch
        const int t0 = 4 * j;
        unsigned pk = 0;
        if (t0 < lenq) {
            // cont: 3+2 float4 = tokens 4j..4j+3 (overread within batch region is safe)
            const float4* gcp = (const float4*)(cont_p + (size_t)(b0 + q) * (NS * 3)) + 3 * j;
            const float4 a0 = gcp[0], a1 = gcp[1], a2 = gcp[2];
            const float4* gcc = (const float4*)(cont_c + (size_t)(b0 + q) * (NS * 2)) + 2 * j;
            const float4 d0 = gcc[0], d1 = gcc[1];

            s_t4[q][t0] = make_float4(a0.x, a0.y, a0.z, d0.x);
            s_y1[q][t0] = d0.y;
            if (t0 + 1 < lenq) { s_t4[q][t0 + 1] = make_float4(a0.w, a1.x, a1.y, d0.z); s_y1[q][t0 + 1] = d0.w; }
            if (t0 + 2 < lenq) { s_t4[q][t0 + 2] = make_float4(a1.z, a1.w, a2.x, d1.x); s_y1[q][t0 + 2] = d1.y; }
            if (t0 + 3 < lenq) { s_t4[q][t0 + 3] = make_float4(a2.y, a2.z, a2.w, d1.z); s_y1[q][t0 + 3] = d1.w; }

            // cat: 5 int4 (cat_p) + 2 int4 (cat_c)
            const int4* gvp = (const int4*)(cat_p + (size_t)(b0 + q) * (NS * 5)) + 5 * j;
            const int4 p0 = gvp[0], p1 = gvp[1], p2 = gvp[2], p3 = gvp[3], p4 = gvp[4];
            const int4* gvc = (const int4*)(cat_c + (size_t)(b0 + q) * (NS * 2)) + 2 * j;
            const int4 c0v = gvc[0], c1v = gvc[1];

            int* hq = s_hist[q];
            pk += (unsigned)p0.x + ((unsigned)p0.y << 10) + ((unsigned)p0.z << 20);
            atomicAdd(&hq[H_JOB + p0.w], 1);
            atomicAdd(&hq[H_REP + p1.x], 1);
            atomicAdd(&hq[H_PLACE + c0v.x], 1);
            atomicAdd(&hq[H_ADD + c0v.y], 1);
            if (t0 + 1 < lenq) {
                pk += (unsigned)p1.y + ((unsigned)p1.z << 10) + ((unsigned)p1.w << 20);
                atomicAdd(&hq[H_JOB + p2.x], 1);
                atomicAdd(&hq[H_REP + p2.y], 1);
                atomicAdd(&hq[H_PLACE + c0v.z], 1);
                atomicAdd(&hq[H_ADD + c0v.w], 1);
            }
            if (t0 + 2 < lenq) {
                pk += (unsigned)p2.z + ((unsigned)p2.w << 10) + ((unsigned)p3.x << 20);
                atomicAdd(&hq[H_JOB + p3.y], 1);
                atomicAdd(&hq[H_REP + p3.z], 1);
                atomicAdd(&hq[H_PLACE + c1v.x], 1);
                atomicAdd(&hq[H_ADD + c1v.y], 1);
            }
            if (t0 + 3 < lenq) {
                pk += (unsigned)p3.w + ((unsigned)p4.x << 10) + ((unsigned)p4.y << 20);
                atomicAdd(&hq[H_JOB + p4.z], 1);
                atomicAdd(&hq[H_REP + p4.w], 1);
                atomicAdd(&hq[H_PLACE + c1v.z], 1);
                atomicAdd(&hq[H_ADD + c1v.w], 1);
            }
        }
        const unsigned wsum = __reduce_add_sync(0xffffffffu, pk);
        if (lane == 0) atomicAdd(&s_binpack[q], wsum);
    }
    __syncthreads();

    // ---- Phase B: warp = (q, h); lane = output dim; contiguous halves, 2 tok/iter ----
    {
        const float wa0 = w_p1[lane], wa1 = w_p1[32 + lane], wa2 = w_p1[64 + lane], ba = b_p1[lane];
        const float wb0 = w_c1[lane], wb1 = w_c1[32 + lane], bb = b_c1[lane];

        const int mid = lenq >> 1;
        const int tbeg = h ? mid : 0;
        const int tend = h ? lenq : mid;

        float ap0 = 0.f, ac0 = 0.f, ap1 = 0.f, ac1 = 0.f;
        int t = tbeg;
        #pragma unroll 2
        for (; t + 2 <= tend; t += 2) {
            const float4 v0 = s_t4[q][t];
            const float4 v1 = s_t4[q][t + 1];
            const float ya = s_y1[q][t];
            const float yb = s_y1[q][t + 1];
            float a = fmaf(v0.z, wa2, fmaf(v0.y, wa1, fmaf(v0.x, wa0, ba)));
            float b = fmaf(v1.z, wa2, fmaf(v1.y, wa1, fmaf(v1.x, wa0, ba)));
            ap0 += fmaxf(a, 0.f);
            ap1 += fmaxf(b, 0.f);
            float c = fmaf(ya, wb1, fmaf(v0.w, wb0, bb));
            float d = fmaf(yb, wb1, fmaf(v1.w, wb0, bb));
            ac0 += fmaxf(c, 0.f);
            ac1 += fmaxf(d, 0.f);
        }
        if (t < tend) {
            const float4 v0 = s_t4[q][t];
            const float ya = s_y1[q][t];
            float a = fmaf(v0.z, wa2, fmaf(v0.y, wa1, fmaf(v0.x, wa0, ba)));
            ap0 += fmaxf(a, 0.f);
            float c = fmaf(ya, wb1, fmaf(v0.w, wb0, bb));
            ac0 += fmaxf(c, 0.f);
        }
        s_redA[q][h][lane] = ap0 + ap1;
        s_redC[q][h][lane] = ac0 + ac1;
    }
    __syncthreads();

    // ---- reduce the 2 halves per batch ----
    {
        const int rq = tid >> 6;        // 0..3
        const int rem = tid & 63;
        if (rem < 32) {
            s_apsum[rq][rem] = s_redA[rq][0][rem] + s_redA[rq][1][rem];
        } else {
            const int l = rem - 32;
            s_acsum[rq][l] = s_redC[rq][0][l] + s_redC[rq][1][l];
        }
    }
    __syncthreads();

    // ---- tail: 16 warp-jobs (4 batches x 4 segments), 2 rounds over 8 warps ----
    #pragma unroll
    for (int round = 0; round < 2; round++) {
        const int job = w + round * 8;       // 0..15
        const int jq = job & 3;
        const int seg = job >> 2;
        const float flen = (float)lengths[b0 + jq];
        const float inv_len = 1.0f / flen;
        const int dd = lane;

        if (seg == 0) {
            const unsigned bp = s_binpack[jq];
            const float n1g = (float)(bp & 1023u);
            const float n1k = (float)((bp >> 10) & 1023u);
            const float n1p = (float)((bp >> 20) & 1023u);
            float e = (flen - n1g) * eg[dd]  + n1g * eg[32 + dd]
                    + (flen - n1k) * ek[dd]  + n1k * ek[32 + dd]
                    + (flen - n1p) * epr[dd] + n1p * epr[32 + dd];
            #pragma unroll
            for (int v = 0; v < 11; v++) e = fmaf((float)s_hist[jq][H_JOB + v], ejob[v * 32 + dd], e);
            #pragma unroll
            for (int v = 0; v < 34; v++) e = fmaf((float)s_hist[jq][H_REP + v], erep[v * 32 + dd], e);
            s_pool[jq][dd] = e * (inv_len * 0.2f);
        } else if (seg == 1) {
            float e = 0.f;
            #pragma unroll
            for (int v = 0; v < 19; v++) e = fmaf((float)s_hist[jq][H_PLACE + v], epl[v * 32 + dd], e);
            #pragma unroll
            for (int v = 0; v < 31; v++) e = fmaf((float)s_hist[jq][H_ADD + v], eadd[v * 32 + dd], e);
            s_pool[jq][32 + dd] = e * (inv_len * 0.5f);
        } else if (seg == 2) {
            float s = 0.f;
            #pragma unroll
            for (int k = 0; k < 32; k++) s = fmaf(s_apsum[jq][k], w_p2[k * 32 + dd], s);
            s_pool[jq][64 + dd] = fmaf(s, inv_len, b_p2[dd]);
        } else {
            float s = 0.f;
            #pragma unroll
            for (int k = 0; k < 32; k++) s = fmaf(s_acsum[jq][k], w_c2[k * 32 + dd], s);
            s_pool[jq][96 + dd] = fmaf(s, inv_len, b_c2[dd]);
        }
    }
    __syncthreads();

    // ---- fc1 (128->64): thread = (dc=q, j); weights in 2 chunks of 16 (reg pressure) ----
    {
        const int jcol = h * 32 + lane;
        const float* wp = w_fc1 + (q * 32) * 64 + jcol;
        float acc[NQ];
        #pragma unroll
        for (int bq = 0; bq < NQ; bq++) acc[bq] = 0.f;
        #pragma unroll
        for (int c = 0; c < 2; c++) {
            float wv[16];
            #pragma unroll
            for (int i = 0; i < 16; i++) wv[i] = wp[(c * 16 + i) * 64];
            #pragma unroll
            for (int bq = 0; bq < NQ; bq++) {
                float s = acc[bq];
                #pragma unroll
                for (int i = 0; i < 16; i++)
                    s = fmaf(wv[i], s_pool[bq][q * 32 + c * 16 + i], s);
                acc[bq] = s;
            }
        }
        #pragma unroll
        for (int bq = 0; bq < NQ; bq++) s_part[bq][q][jcol] = acc[bq];
    }
    __syncthreads();

    // ---- combine partials + bias + relu: 256 threads = (batch, j) ----
    {
        const int bq = tid >> 6;
        const int jj = tid & 63;
        float hh = b_fc1[jj] + ((s_part[bq][0][jj] + s_part[bq][1][jj]) +
                                (s_part[bq][2][jj] + s_part[bq][3][jj]));
        s_h1[bq][jj] = fmaxf(hh, 0.f);
    }
    __syncthreads();

    // ---- fc2 (64->2, relu): warp = (q, o); warp reduce ----
    {
        const int o = h;
        float s = fmaf(s_h1[q][lane], w_fc2[lane * 2 + o],
                       s_h1[q][lane + 32] * w_fc2[(lane + 32) * 2 + o]);
        s += __shfl_xor_sync(0xffffffffu, s, 16);
        s += __shfl_xor_sync(0xffffffffu, s, 8);
        s += __shfl_xor_sync(0xffffffffu, s, 4);
        s += __shfl_xor_sync(0xffffffffu, s, 2);
        s += __shfl_xor_sync(0xffffffffu, s, 1);
        if (lane == 0) out[(b0 + q) * 2 + o] = fmaxf(s + b_fc2[o], 0.f);
    }
}

extern "C" void kernel_launch(void* const* d_in, const int* in_sizes, int n_in,
                              void* d_out, int out_size)
{
    const float* cont_p = (const float*)d_in[0];
    const float* cont_c = (const float*)d_in[1];
    const int*   cat_p  = (const int*)d_in[2];
    const int*   cat_c  = (const int*)d_in[3];
    const int*   lengths= (const int*)d_in[4];
    const float* w_p1   = (const float*)d_in[5];
    const float* b_p1   = (const float*)d_in[6];
    const float* w_p2   = (const float*)d_in[7];
    const float* b_p2   = (const float*)d_in[8];
    const float* w_c1   = (const float*)d_in[9];
    const float* b_c1   = (const float*)d_in[10];
    const float* w_c2   = (const float*)d_in[11];
    const float* b_c2   = (const float*)d_in[12];
    const float* eg     = (const float*)d_in[13];
    const float* ek     = (const float*)d_in[14];
    const float* epr    = (const float*)d_in[15];
    const float* ejob   = (const float*)d_in[16];
    const float* erep   = (const float*)d_in[17];
    const float* epl    = (const float*)d_in[18];
    const float* eadd   = (const float*)d_in[19];
    const float* w_fc1  = (const float*)d_in[20];
    const float* b_fc1  = (const float*)d_in[21];
    const float* w_fc2  = (const float*)d_in[22];
    const float* b_fc2  = (const float*)d_in[23];
    float* out = (float*)d_out;

    fused4_kernel<<<NB / NQ, 256>>>(cont_p, cont_c, cat_p, cat_c, lengths,
                                    w_p1, b_p1, w_p2, b_p2, w_c1, b_c1, w_c2, b_c2,
                                    eg, ek, epr, ejob, erep, epl, eadd,
                                    w_fc1, b_fc1, w_fc2, b_fc2, out);
}

// round 13
// speedup vs baseline: 1.0954x; 1.0954x over previous
#include <cuda_runtime.h>
#include <cuda_bf16.h>

#define NB 4096
#define NS 256
#define NQ 4          // batches per CTA

// histogram layout: job[11] @0, rep[34] @11, place[19] @45, add[31] @64 -> 95 (pad 96)
#define H_JOB 0
#define H_REP 11
#define H_PLACE 45
#define H_ADD 64

__global__ __launch_bounds__(256, 7)
void fused4_kernel(const float* __restrict__ cont_p, const float* __restrict__ cont_c,
                   const int* __restrict__ cat_p, const int* __restrict__ cat_c,
                   const int* __restrict__ lengths,
                   const float* __restrict__ w_p1, const float* __restrict__ b_p1,
                   const float* __restrict__ w_p2, const float* __restrict__ b_p2,
                   const float* __restrict__ w_c1, const float* __restrict__ b_c1,
                   const float* __restrict__ w_c2, const float* __restrict__ b_c2,
                   const float* __restrict__ eg, const float* __restrict__ ek,
                   const float* __restrict__ epr, const float* __restrict__ ejob,
                   const float* __restrict__ erep, const float* __restrict__ epl,
                   const float* __restrict__ eadd,
                   const float* __restrict__ w_fc1, const float* __restrict__ b_fc1,
                   const float* __restrict__ w_fc2, const float* __restrict__ b_fc2,
                   float* __restrict__ out)
{
    const int tid = threadIdx.x;
    const int lane = tid & 31;
    const int w = tid >> 5;
    const int b0 = blockIdx.x * NQ;
    const int q = w >> 1;          // warp's batch (0..3)
    const int h = w & 1;           // warp's half (0/1)

    __shared__ float4 s_t4[NQ][NS];      // 16 KB {x0,x1,x2,y0}
    __shared__ float  s_y1[NQ][NS];      // 4 KB
    __shared__ int    s_hist[NQ][96];    // 1.5 KB
    __shared__ unsigned s_binpack[NQ];
    __shared__ float s_redA[NQ][2][32];  // later reused as s_h1[NQ][64]
    __shared__ float s_redC[NQ][2][32];
    __shared__ float s_apsum[NQ][32];
    __shared__ float s_acsum[NQ][32];
    __shared__ float s_pool[NQ][128];    // 2 KB
    __shared__ float s_part[NQ][4][64];  // 4 KB

    float (*s_h1)[64] = (float (*)[64])&s_redA[0][0][0];   // overlay (dead after halves-reduce)

    for (int i = tid; i < NQ * 96; i += 256) ((int*)s_hist)[i] = 0;
    if (tid < NQ) s_binpack[tid] = 0u;
    __syncthreads();

    const int lenq = lengths[b0 + q];    // uniform per warp (broadcast)

    // ---- Phase A: thread j owns tokens 4j..4j+3 of batch q; two short-live-range scopes ----
    {
        const int j = h * 32 + lane;     // 0..63 within batch
        const int t0 = 4 * j;
        const bool act = (t0 < lenq);

        // scope 1: continuous features -> staging (unconditional within active group;
        // tokens >= lenq are staged with garbage but never read)
        if (act) {
            const float4* gcp = (const float4*)(cont_p + (size_t)(b0 + q) * (NS * 3)) + 3 * j;
            const float4 a0 = gcp[0], a1 = gcp[1], a2 = gcp[2];
            const float4* gcc = (const float4*)(cont_c + (size_t)(b0 + q) * (NS * 2)) + 2 * j;
            const float4 d0 = gcc[0], d1 = gcc[1];

            s_t4[q][t0]     = make_float4(a0.x, a0.y, a0.z, d0.x);
            s_t4[q][t0 + 1] = make_float4(a0.w, a1.x, a1.y, d0.z);
            s_t4[q][t0 + 2] = make_float4(a1.z, a1.w, a2.x, d1.x);
            s_t4[q][t0 + 3] = make_float4(a2.y, a2.z, a2.w, d1.z);
            *(float4*)&s_y1[q][t0] = make_float4(d0.y, d0.w, d1.y, d1.w);
        }

        // scope 2: categorical features -> histograms (guards required: side effects)
        unsigned pk = 0;
        if (act) {
            const int4* gvp = (const int4*)(cat_p + (size_t)(b0 + q) * (NS * 5)) + 5 * j;
            const int4 p0 = gvp[0], p1 = gvp[1], p2 = gvp[2], p3 = gvp[3], p4 = gvp[4];
            const int4* gvc = (const int4*)(cat_c + (size_t)(b0 + q) * (NS * 2)) + 2 * j;
            const int4 c0v = gvc[0], c1v = gvc[1];

            int* hq = s_hist[q];
            pk += (unsigned)p0.x + ((unsigned)p0.y << 10) + ((unsigned)p0.z << 20);
            atomicAdd(&hq[H_JOB + p0.w], 1);
            atomicAdd(&hq[H_REP + p1.x], 1);
            atomicAdd(&hq[H_PLACE + c0v.x], 1);
            atomicAdd(&hq[H_ADD + c0v.y], 1);
            if (t0 + 1 < lenq) {
                pk += (unsigned)p1.y + ((unsigned)p1.z << 10) + ((unsigned)p1.w << 20);
                atomicAdd(&hq[H_JOB + p2.x], 1);
                atomicAdd(&hq[H_REP + p2.y], 1);
                atomicAdd(&hq[H_PLACE + c0v.z], 1);
                atomicAdd(&hq[H_ADD + c0v.w], 1);
            }
            if (t0 + 2 < lenq) {
                pk += (unsigned)p2.z + ((unsigned)p2.w << 10) + ((unsigned)p3.x << 20);
                atomicAdd(&hq[H_JOB + p3.y], 1);
                atomicAdd(&hq[H_REP + p3.z], 1);
                atomicAdd(&hq[H_PLACE + c1v.x], 1);
                atomicAdd(&hq[H_ADD + c1v.y], 1);
            }
            if (t0 + 3 < lenq) {
                pk += (unsigned)p3.w + ((unsigned)p4.x << 10) + ((unsigned)p4.y << 20);
                atomicAdd(&hq[H_JOB + p4.z], 1);
                atomicAdd(&hq[H_REP + p4.w], 1);
                atomicAdd(&hq[H_PLACE + c1v.z], 1);
                atomicAdd(&hq[H_ADD + c1v.w], 1);
            }
        }
        const unsigned wsum = __reduce_add_sync(0xffffffffu, pk);
        if (lane == 0) atomicAdd(&s_binpack[q], wsum);
    }
    __syncthreads();

    // ---- Phase B: warp = (q, h); lane = output dim; stride-2 over tokens (R11 proven) ----
    {
        const float wa0 = w_p1[lane], wa1 = w_p1[32 + lane], wa2 = w_p1[64 + lane], ba = b_p1[lane];
        const float wb0 = w_c1[lane], wb1 = w_c1[32 + lane], bb = b_c1[lane];

        float ap_acc = 0.f, ac_acc = 0.f;
        #pragma unroll 4
        for (int t = h; t < lenq; t += 2) {
            const float4 v = s_t4[q][t];
            const float y1 = s_y1[q][t];
            float ap = fmaf(v.z, wa2, fmaf(v.y, wa1, fmaf(v.x, wa0, ba)));
            ap_acc += fmaxf(ap, 0.f);
            float ac = fmaf(y1, wb1, fmaf(v.w, wb0, bb));
            ac_acc += fmaxf(ac, 0.f);
        }
        s_redA[q][h][lane] = ap_acc;
        s_redC[q][h][lane] = ac_acc;
    }
    __syncthreads();

    // ---- reduce the 2 halves per batch ----
    {
        const int rq = tid >> 6;        // 0..3
        const int rem = tid & 63;
        if (rem < 32) {
            s_apsum[rq][rem] = s_redA[rq][0][rem] + s_redA[rq][1][rem];
        } else {
            const int l = rem - 32;
            s_acsum[rq][l] = s_redC[rq][0][l] + s_redC[rq][1][l];
        }
    }
    __syncthreads();
    // (s_redA is dead from here; its space is reused as s_h1)

    // ---- tail: 16 warp-jobs (4 batches x 4 segments), 2 rounds over 8 warps ----
    #pragma unroll
    for (int round = 0; round < 2; round++) {
        const int job = w + round * 8;       // 0..15
        const int jq = job & 3;
        const int seg = job >> 2;
        const float flen = (float)lengths[b0 + jq];
        const float inv_len = 1.0f / flen;
        const int dd = lane;

        if (seg == 0) {
            const unsigned bp = s_binpack[jq];
            const float n1g = (float)(bp & 1023u);
            const float n1k = (float)((bp >> 10) & 1023u);
            const float n1p = (float)((bp >> 20) & 1023u);
            float e = (flen - n1g) * eg[dd]  + n1g * eg[32 + dd]
                    + (flen - n1k) * ek[dd]  + n1k * ek[32 + dd]
                    + (flen - n1p) * epr[dd] + n1p * epr[32 + dd];
            #pragma unroll
            for (int v = 0; v < 11; v++) e = fmaf((float)s_hist[jq][H_JOB + v], ejob[v * 32 + dd], e);
            #pragma unroll
            for (int v = 0; v < 34; v++) e = fmaf((float)s_hist[jq][H_REP + v], erep[v * 32 + dd], e);
            s_pool[jq][dd] = e * (inv_len * 0.2f);
        } else if (seg == 1) {
            float e = 0.f;
            #pragma unroll
            for (int v = 0; v < 19; v++) e = fmaf((float)s_hist[jq][H_PLACE + v], epl[v * 32 + dd], e);
            #pragma unroll
            for (int v = 0; v < 31; v++) e = fmaf((float)s_hist[jq][H_ADD + v], eadd[v * 32 + dd], e);
            s_pool[jq][32 + dd] = e * (inv_len * 0.5f);
        } else if (seg == 2) {
            float s = 0.f;
            #pragma unroll
            for (int k = 0; k < 32; k++) s = fmaf(s_apsum[jq][k], w_p2[k * 32 + dd], s);
            s_pool[jq][64 + dd] = fmaf(s, inv_len, b_p2[dd]);
        } else {
            float s = 0.f;
            #pragma unroll
            for (int k = 0; k < 32; k++) s = fmaf(s_acsum[jq][k], w_c2[k * 32 + dd], s);
            s_pool[jq][96 + dd] = fmaf(s, inv_len, b_c2[dd]);
        }
    }
    __syncthreads();

    // ---- fc1 (128->64): thread = (dc=q, j); weights in 2 chunks of 16 (reg pressure) ----
    {
        const int jcol = h * 32 + lane;
        const float* wp = w_fc1 + (q * 32) * 64 + jcol;
        float acc[NQ];
        #pragma unroll
        for (int bq = 0; bq < NQ; bq++) acc[bq] = 0.f;
        #pragma unroll
        for (int c = 0; c < 2; c++) {
            float wv[16];
            #pragma unroll
            for (int i = 0; i < 16; i++) wv[i] = wp[(c * 16 + i) * 64];
            #pragma unroll
            for (int bq = 0; bq < NQ; bq++) {
                float s = acc[bq];
                #pragma unroll
                for (int i = 0; i < 16; i++)
                    s = fmaf(wv[i], s_pool[bq][q * 32 + c * 16 + i], s);
                acc[bq] = s;
            }
        }
        #pragma unroll
        for (int bq = 0; bq < NQ; bq++) s_part[bq][q][jcol] = acc[bq];
    }
    __syncthreads();

    // ---- combine partials + bias + relu: 256 threads = (batch, j) ----
    {
        const int bq = tid >> 6;
        const int jj = tid & 63;
        float hh = b_fc1[jj] + ((s_part[bq][0][jj] + s_part[bq][1][jj]) +
                                (s_part[bq][2][jj] + s_part[bq][3][jj]));
        s_h1[bq][jj] = fmaxf(hh, 0.f);
    }
    __syncthreads();

    // ---- fc2 (64->2, relu): warp = (q, o); warp reduce ----
    {
        const int o = h;
        float s = fmaf(s_h1[q][lane], w_fc2[lane * 2 + o],
                       s_h1[q][lane + 32] * w_fc2[(lane + 32) * 2 + o]);
        s += __shfl_xor_sync(0xffffffffu, s, 16);
        s += __shfl_xor_sync(0xffffffffu, s, 8);
        s += __shfl_xor_sync(0xffffffffu, s, 4);
        s += __shfl_xor_sync(0xffffffffu, s, 2);
        s += __shfl_xor_sync(0xffffffffu, s, 1);
        if (lane == 0) out[(b0 + q) * 2 + o] = fmaxf(s + b_fc2[o], 0.f);
    }
}

extern "C" void kernel_launch(void* const* d_in, const int* in_sizes, int n_in,
                              void* d_out, int out_size)
{
    const float* cont_p = (const float*)d_in[0];
    const float* cont_c = (const float*)d_in[1];
    const int*   cat_p  = (const int*)d_in[2];
    const int*   cat_c  = (const int*)d_in[3];
    const int*   lengths= (const int*)d_in[4];
    const float* w_p1   = (const float*)d_in[5];
    const float* b_p1   = (const float*)d_in[6];
    const float* w_p2   = (const float*)d_in[7];
    const float* b_p2   = (const float*)d_in[8];
    const float* w_c1   = (const float*)d_in[9];
    const float* b_c1   = (const float*)d_in[10];
    const float* w_c2   = (const float*)d_in[11];
    const float* b_c2   = (const float*)d_in[12];
    const float* eg     = (const float*)d_in[13];
    const float* ek     = (const float*)d_in[14];
    const float* epr    = (const float*)d_in[15];
    const float* ejob   = (const float*)d_in[16];
    const float* erep   = (const float*)d_in[17];
    const float* epl    = (const float*)d_in[18];
    const float* eadd   = (const float*)d_in[19];
    const float* w_fc1  = (const float*)d_in[20];
    const float* b_fc1  = (const float*)d_in[21];
    const float* w_fc2  = (const float*)d_in[22];
    const float* b_fc2  = (const float*)d_in[23];
    float* out = (float*)d_out;

    fused4_kernel<<<NB / NQ, 256>>>(cont_p, cont_c, cat_p, cat_c, lengths,
                                    w_p1, b_p1, w_p2, b_p2, w_c1, b_c1, w_c2, b_c2,
                                    eg, ek, epr, ejob, erep, epl, eadd,
                                    w_fc1, b_fc1, w_fc2, b_fc2, out);
}

// round 14
// speedup vs baseline: 1.1781x; 1.0755x over previous
#include <cuda_runtime.h>
#include <cuda_bf16.h>

#define NB 4096
#define NS 256
#define NQ 4          // batches per CTA

// histogram layout: job[11] @0, rep[34] @11, place[19] @45, add[31] @64 -> 95 (pad 96)
#define H_JOB 0
#define H_REP 11
#define H_PLACE 45
#define H_ADD 64

__global__ __launch_bounds__(256, 5)
void fused4_kernel(const float* __restrict__ cont_p, const float* __restrict__ cont_c,
                   const int* __restrict__ cat_p, const int* __restrict__ cat_c,
                   const int* __restrict__ lengths,
                   const float* __restrict__ w_p1, const float* __restrict__ b_p1,
                   const float* __restrict__ w_p2, const float* __restrict__ b_p2,
                   const float* __restrict__ w_c1, const float* __restrict__ b_c1,
                   const float* __restrict__ w_c2, const float* __restrict__ b_c2,
                   const float* __restrict__ eg, const float* __restrict__ ek,
                   const float* __restrict__ epr, const float* __restrict__ ejob,
                   const float* __restrict__ erep, const float* __restrict__ epl,
                   const float* __restrict__ eadd,
                   const float* __restrict__ w_fc1, const float* __restrict__ b_fc1,
                   const float* __restrict__ w_fc2, const float* __restrict__ b_fc2,
                   float* __restrict__ out)
{
    const int tid = threadIdx.x;
    const int lane = tid & 31;
    const int w = tid >> 5;
    const int b0 = blockIdx.x * NQ;
    const int q = w >> 1;          // warp's batch (0..3)
    const int h = w & 1;           // warp's half (0/1)

    __shared__ float4 s_t4[NQ][NS];      // 16 KB {x0,x1,x2,y0}
    __shared__ float  s_y1[NQ][NS];      // 4 KB
    __shared__ int    s_hist[NQ][96];    // 1.5 KB
    __shared__ unsigned s_binpack[NQ];
    __shared__ float s_redA[NQ][2][32];  // later reused as s_h1[NQ][64]
    __shared__ float s_redC[NQ][2][32];
    __shared__ float s_apsum[NQ][32];
    __shared__ float s_acsum[NQ][32];
    __shared__ float s_pool[NQ][128];    // 2 KB
    __shared__ float s_part[NQ][4][64];  // 4 KB

    float (*s_h1)[64] = (float (*)[64])&s_redA[0][0][0];   // overlay (dead after halves-reduce)

    for (int i = tid; i < NQ * 96; i += 256) ((int*)s_hist)[i] = 0;
    if (tid < NQ) s_binpack[tid] = 0u;
    __syncthreads();

    const int lenq = lengths[b0 + q];    // uniform per warp (broadcast)

    const int j = h * 32 + lane;         // 0..63 within batch
    const int t0 = 4 * j;
    const bool act = (t0 < lenq);

    // ---- Phase A-1: continuous staging (short live range), cat loads held in regs ----
    int4 p0, p1, p2, p3, p4, c0v, c1v;
    {
        if (act) {
            const float4* gcp = (const float4*)(cont_p + (size_t)(b0 + q) * (NS * 3)) + 3 * j;
            const float4 a0 = gcp[0], a1 = gcp[1], a2 = gcp[2];
            const float4* gcc = (const float4*)(cont_c + (size_t)(b0 + q) * (NS * 2)) + 2 * j;
            const float4 d0 = gcc[0], d1 = gcc[1];

            s_t4[q][t0]     = make_float4(a0.x, a0.y, a0.z, d0.x);
            s_t4[q][t0 + 1] = make_float4(a0.w, a1.x, a1.y, d0.z);
            s_t4[q][t0 + 2] = make_float4(a1.z, a1.w, a2.x, d1.x);
            s_t4[q][t0 + 3] = make_float4(a2.y, a2.z, a2.w, d1.z);
            *(float4*)&s_y1[q][t0] = make_float4(d0.y, d0.w, d1.y, d1.w);

            const int4* gvp = (const int4*)(cat_p + (size_t)(b0 + q) * (NS * 5)) + 5 * j;
            p0 = gvp[0]; p1 = gvp[1]; p2 = gvp[2]; p3 = gvp[3]; p4 = gvp[4];
            const int4* gvc = (const int4*)(cat_c + (size_t)(b0 + q) * (NS * 2)) + 2 * j;
            c0v = gvc[0]; c1v = gvc[1];
        }
    }
    __syncthreads();   // staging visible; NO atomics issued yet, so nothing to drain

    // ---- Phase A-2: fire-and-forget histogram atomics (drain hides under Phase B) ----
    {
        unsigned pk = 0;
        if (act) {
            int* hq = s_hist[q];
            pk += (unsigned)p0.x + ((unsigned)p0.y << 10) + ((unsigned)p0.z << 20);
            atomicAdd(&hq[H_JOB + p0.w], 1);
            atomicAdd(&hq[H_REP + p1.x], 1);
            atomicAdd(&hq[H_PLACE + c0v.x], 1);
            atomicAdd(&hq[H_ADD + c0v.y], 1);
            if (t0 + 1 < lenq) {
                pk += (unsigned)p1.y + ((unsigned)p1.z << 10) + ((unsigned)p1.w << 20);
                atomicAdd(&hq[H_JOB + p2.x], 1);
                atomicAdd(&hq[H_REP + p2.y], 1);
                atomicAdd(&hq[H_PLACE + c0v.z], 1);
                atomicAdd(&hq[H_ADD + c0v.w], 1);
            }
            if (t0 + 2 < lenq) {
                pk += (unsigned)p2.z + ((unsigned)p2.w << 10) + ((unsigned)p3.x << 20);
                atomicAdd(&hq[H_JOB + p3.y], 1);
                atomicAdd(&hq[H_REP + p3.z], 1);
                atomicAdd(&hq[H_PLACE + c1v.x], 1);
                atomicAdd(&hq[H_ADD + c1v.y], 1);
            }
            if (t0 + 3 < lenq) {
                pk += (unsigned)p3.w + ((unsigned)p4.x << 10) + ((unsigned)p4.y << 20);
                atomicAdd(&hq[H_JOB + p4.z], 1);
                atomicAdd(&hq[H_REP + p4.w], 1);
                atomicAdd(&hq[H_PLACE + c1v.z], 1);
                atomicAdd(&hq[H_ADD + c1v.w], 1);
            }
        }
        const unsigned wsum = __reduce_add_sync(0xffffffffu, pk);
        if (lane == 0) atomicAdd(&s_binpack[q], wsum);
    }

    // ---- Phase B: warp = (q, h); lane = output dim; stride-2 over tokens (R11 proven) ----
    {
        const float wa0 = w_p1[lane], wa1 = w_p1[32 + lane], wa2 = w_p1[64 + lane], ba = b_p1[lane];
        const float wb0 = w_c1[lane], wb1 = w_c1[32 + lane], bb = b_c1[lane];

        float ap_acc = 0.f, ac_acc = 0.f;
        #pragma unroll 4
        for (int t = h; t < lenq; t += 2) {
            const float4 v = s_t4[q][t];
            const float y1 = s_y1[q][t];
            float ap = fmaf(v.z, wa2, fmaf(v.y, wa1, fmaf(v.x, wa0, ba)));
            ap_acc += fmaxf(ap, 0.f);
            float ac = fmaf(y1, wb1, fmaf(v.w, wb0, bb));
            ac_acc += fmaxf(ac, 0.f);
        }
        s_redA[q][h][lane] = ap_acc;
        s_redC[q][h][lane] = ac_acc;
    }
    __syncthreads();   // also drains any atomic residue

    // ---- reduce the 2 halves per batch ----
    {
        const int rq = tid >> 6;        // 0..3
        const int rem = tid & 63;
        if (rem < 32) {
            s_apsum[rq][rem] = s_redA[rq][0][rem] + s_redA[rq][1][rem];
        } else {
            const int l = rem - 32;
            s_acsum[rq][l] = s_redC[rq][0][l] + s_redC[rq][1][l];
        }
    }
    __syncthreads();
    // (s_redA is dead from here; its space is reused as s_h1)

    // ---- tail: 16 warp-jobs (4 batches x 4 segments), 2 rounds over 8 warps ----
    #pragma unroll
    for (int round = 0; round < 2; round++) {
        const int job = w + round * 8;       // 0..15
        const int jq = job & 3;
        const int seg = job >> 2;
        const float flen = (float)lengths[b0 + jq];
        const float inv_len = 1.0f / flen;
        const int dd = lane;

        if (seg == 0) {
            const unsigned bp = s_binpack[jq];
            const float n1g = (float)(bp & 1023u);
            const float n1k = (float)((bp >> 10) & 1023u);
            const float n1p = (float)((bp >> 20) & 1023u);
            float e = (flen - n1g) * eg[dd]  + n1g * eg[32 + dd]
                    + (flen - n1k) * ek[dd]  + n1k * ek[32 + dd]
                    + (flen - n1p) * epr[dd] + n1p * epr[32 + dd];
            #pragma unroll
            for (int v = 0; v < 11; v++) e = fmaf((float)s_hist[jq][H_JOB + v], ejob[v * 32 + dd], e);
            #pragma unroll
            for (int v = 0; v < 34; v++) e = fmaf((float)s_hist[jq][H_REP + v], erep[v * 32 + dd], e);
            s_pool[jq][dd] = e * (inv_len * 0.2f);
        } else if (seg == 1) {
            float e = 0.f;
            #pragma unroll
            for (int v = 0; v < 19; v++) e = fmaf((float)s_hist[jq][H_PLACE + v], epl[v * 32 + dd], e);
            #pragma unroll
            for (int v = 0; v < 31; v++) e = fmaf((float)s_hist[jq][H_ADD + v], eadd[v * 32 + dd], e);
            s_pool[jq][32 + dd] = e * (inv_len * 0.5f);
        } else if (seg == 2) {
            float s = 0.f;
            #pragma unroll
            for (int k = 0; k < 32; k++) s = fmaf(s_apsum[jq][k], w_p2[k * 32 + dd], s);
            s_pool[jq][64 + dd] = fmaf(s, inv_len, b_p2[dd]);
        } else {
            float s = 0.f;
            #pragma unroll
            for (int k = 0; k < 32; k++) s = fmaf(s_acsum[jq][k], w_c2[k * 32 + dd], s);
            s_pool[jq][96 + dd] = fmaf(s, inv_len, b_c2[dd]);
        }
    }
    __syncthreads();

    // ---- fc1 (128->64): thread = (dc=q, j); weights in 2 chunks of 16 (reg pressure) ----
    {
        const int jcol = h * 32 + lane;
        const float* wp = w_fc1 + (q * 32) * 64 + jcol;
        float acc[NQ];
        #pragma unroll
        for (int bq = 0; bq < NQ; bq++) acc[bq] = 0.f;
        #pragma unroll
        for (int c = 0; c < 2; c++) {
            float wv[16];
            #pragma unroll
            for (int i = 0; i < 16; i++) wv[i] = wp[(c * 16 + i) * 64];
            #pragma unroll
            for (int bq = 0; bq < NQ; bq++) {
                float s = acc[bq];
                #pragma unroll
                for (int i = 0; i < 16; i++)
                    s = fmaf(wv[i], s_pool[bq][q * 32 + c * 16 + i], s);
                acc[bq] = s;
            }
        }
        #pragma unroll
        for (int bq = 0; bq < NQ; bq++) s_part[bq][q][jcol] = acc[bq];
    }
    __syncthreads();

    // ---- combine partials + bias + relu: 256 threads = (batch, j) ----
    {
        const int bq = tid >> 6;
        const int jj = tid & 63;
        float hh = b_fc1[jj] + ((s_part[bq][0][jj] + s_part[bq][1][jj]) +
                                (s_part[bq][2][jj] + s_part[bq][3][jj]));
        s_h1[bq][jj] = fmaxf(hh, 0.f);
    }
    __syncthreads();

    // ---- fc2 (64->2, relu): warp = (q, o); warp reduce ----
    {
        const int o = h;
        float s = fmaf(s_h1[q][lane], w_fc2[lane * 2 + o],
                       s_h1[q][lane + 32] * w_fc2[(lane + 32) * 2 + o]);
        s += __shfl_xor_sync(0xffffffffu, s, 16);
        s += __shfl_xor_sync(0xffffffffu, s, 8);
        s += __shfl_xor_sync(0xffffffffu, s, 4);
        s += __shfl_xor_sync(0xffffffffu, s, 2);
        s += __shfl_xor_sync(0xffffffffu, s, 1);
        if (lane == 0) out[(b0 + q) * 2 + o] = fmaxf(s + b_fc2[o], 0.f);
    }
}

extern "C" void kernel_launch(void* const* d_in, const int* in_sizes, int n_in,
                              void* d_out, int out_size)
{
    const float* cont_p = (const float*)d_in[0];
    const float* cont_c = (const float*)d_in[1];
    const int*   cat_p  = (const int*)d_in[2];
    const int*   cat_c  = (const int*)d_in[3];
    const int*   lengths= (const int*)d_in[4];
    const float* w_p1   = (const float*)d_in[5];
    const float* b_p1   = (const float*)d_in[6];
    const float* w_p2   = (const float*)d_in[7];
    const float* b_p2   = (const float*)d_in[8];
    const float* w_c1   = (const float*)d_in[9];
    const float* b_c1   = (const float*)d_in[10];
    const float* w_c2   = (const float*)d_in[11];
    const float* b_c2   = (const float*)d_in[12];
    const float* eg     = (const float*)d_in[13];
    const float* ek     = (const float*)d_in[14];
    const float* epr    = (const float*)d_in[15];
    const float* ejob   = (const float*)d_in[16];
    const float* erep   = (const float*)d_in[17];
    const float* epl    = (const float*)d_in[18];
    const float* eadd   = (const float*)d_in[19];
    const float* w_fc1  = (const float*)d_in[20];
    const float* b_fc1  = (const float*)d_in[21];
    const float* w_fc2  = (const float*)d_in[22];
    const float* b_fc2  = (const float*)d_in[23];
    float* out = (float*)d_out;

    fused4_kernel<<<NB / NQ, 256>>>(cont_p, cont_c, cat_p, cat_c, lengths,
                                    w_p1, b_p1, w_p2, b_p2, w_c1, b_c1, w_c2, b_c2,
                                    eg, ek, epr, ejob, erep, epl, eadd,
                                    w_fc1, b_fc1, w_fc2, b_fc2, out);
}